// round 15
// baseline (speedup 1.0000x reference)
#include <cuda_runtime.h>
#include <math.h>

#define TT 4
#define BB 4
#define TBn 16
#define Cn 96
#define Hn 56
#define Wn 56
#define Ln 3136
#define PLANE (Cn*Ln)          /* 301056 */
#define TOT (TBn*Cn*Ln)        /* 4816896 */
#define SROW 3192              /* skewed smem row size */

// ---------------- scratch (device globals; no allocation) ----------------
__device__ float g_bufA[TOT];
__device__ float g_bufB[TOT];
__device__ float g_bufT[TOT];
__device__ float g_dbl[TBn*4*Ln*8];     // (tb,k,l,8)
__device__ float g_ya[TOT];             // combined ys0 + rev(ys2)
__device__ float g_t1t[TOT];            // combined+transposed ys1 + rev(ys3)
__device__ float g_wc[9*Cn*Cn];         // conv weights reordered [tap][ci][co]
__device__ unsigned int g_msk[TBn*Ln*3];// spike bitmasks: [tb][l][3 words of 32 ch]

// ---------------- helpers ----------------
__device__ __forceinline__ float softplus_fast(float x){
    return (x > 15.f) ? x : __logf(1.f + __expf(x));
}
__device__ __forceinline__ float siluf(float v){
    return v * (1.f / (1.f + expf(-v)));
}

// packed fp32x2 helpers (Blackwell — elementwise IEEE fp32, 2 lanes/instr)
__device__ __forceinline__ unsigned long long pack2(float lo, float hi){
    unsigned long long r;
    asm("mov.b64 %0, {%1, %2};" : "=l"(r) : "r"(__float_as_uint(lo)), "r"(__float_as_uint(hi)));
    return r;
}
__device__ __forceinline__ void unpack2(unsigned long long v, float& lo, float& hi){
    unsigned int a, b;
    asm("mov.b64 {%0, %1}, %2;" : "=r"(a), "=r"(b) : "l"(v));
    lo = __uint_as_float(a); hi = __uint_as_float(b);
}
#define FMA2(acc, a, b) asm("fma.rn.f32x2 %0, %1, %2, %0;" : "+l"(acc) : "l"(a), "l"(b))

// ---------------- conv weight reorder: (co,ci,ky,kx) -> [tap][ci][co] ----------------
__global__ void wreorder_kernel(const float* __restrict__ Win, float* __restrict__ Wt){
    int i = blockIdx.x*blockDim.x + threadIdx.x;
    if (i >= 9*96*96) return;
    int tap = i % 9;
    int ci  = (i / 9) % 96;
    int co  = i / (9*96);
    Wt[tap*9216 + ci*96 + co] = Win[i];
}

// ---------------- pointwise 96x96 GEMM (64-wide tiles, 6co x 4l, FFMA2 + LDS.64 weights) ---
#define GSTR 98
__global__ void __launch_bounds__(256) pw_gemm_kernel(
    const float* __restrict__ X, const float* __restrict__ Wm,
    const float* __restrict__ bias, float* __restrict__ Y)
{
    extern __shared__ float sm[];
    float* Ws = sm;                 // [k][co] stride 98
    float* Xs = sm + 96*GSTR;       // [k][64]
    int tb = blockIdx.y;
    int lt = blockIdx.x;
    int tid = threadIdx.x;

    for (int i = tid; i < 96*96; i += 256){
        int co = i / 96, k = i - co*96;
        Ws[k*GSTR + co] = Wm[i];
    }
    const float* Xp = X + (size_t)tb*PLANE + lt*64;
    for (int i = tid; i < 96*64; i += 256){
        int k = i >> 6, j = i & 63;
        Xs[i] = Xp[(size_t)k*Ln + j];
    }
    __syncthreads();

    int tx = tid & 15, ty = tid >> 4;
    unsigned long long acc[6][2];
    #pragma unroll
    for (int i = 0; i < 6; i++){ acc[i][0] = 0ull; acc[i][1] = 0ull; }

    #pragma unroll 4
    for (int k = 0; k < 96; k++){
        float4 a = *(const float4*)(Xs + k*64 + tx*4);
        unsigned long long x01 = pack2(a.x, a.y);
        unsigned long long x23 = pack2(a.z, a.w);
        const float2* wrow = (const float2*)(Ws + k*GSTR + ty*6);
        float2 w01 = wrow[0], w23 = wrow[1], w45 = wrow[2];
        float wv[6] = {w01.x, w01.y, w23.x, w23.y, w45.x, w45.y};
        #pragma unroll
        for (int i = 0; i < 6; i++){
            unsigned long long ww = pack2(wv[i], wv[i]);
            FMA2(acc[i][0], ww, x01);
            FMA2(acc[i][1], ww, x23);
        }
    }
    #pragma unroll
    for (int i = 0; i < 6; i++){
        int co = ty*6 + i;
        float bv = bias ? bias[co] : 0.f;
        float o0, o1, o2, o3;
        unpack2(acc[i][0], o0, o1);
        unpack2(acc[i][1], o2, o3);
        float* yp = Y + (size_t)tb*PLANE + (size_t)co*Ln + lt*64 + tx*4;
        *(float4*)yp = make_float4(o0+bv, o1+bv, o2+bv, o3+bv);
    }
}

// ---------------- LIF over 16 steps -> channel bitmasks ----------------
__global__ void lif16_kernel(const float* __restrict__ X, unsigned int* __restrict__ M){
    int tid = blockIdx.x*blockDim.x + threadIdx.x;
    if (tid >= Ln*3) return;
    int w3 = tid / Ln;
    int l  = tid - w3*Ln;
    float v[32];
    #pragma unroll
    for (int c = 0; c < 32; c++) v[c] = 0.f;
    for (int t = 0; t < TBn; t++){
        unsigned int m = 0u;
        #pragma unroll
        for (int c = 0; c < 32; c++){
            float x = X[((size_t)t*Cn + w3*32 + c)*Ln + l];
            v[c] += (x - v[c]) * 0.5f;
            bool s = (v[c] >= 1.0f);
            if (s) m |= (1u << c);
            v[c] = s ? 0.f : v[c];
        }
        M[((size_t)t*Ln + l)*3 + w3] = m;
    }
}

// ---------------- sparse full 3x3 conv (R10 proven config) ----------------
#define MROWS 4
#define MCOLS 58
#define WPAD 98
__global__ void __launch_bounds__(256, 3) conv3x3_kernel(
    const unsigned int* __restrict__ Msk, const float* __restrict__ Wt,
    const float* __restrict__ bias, float* __restrict__ Y)
{
    extern __shared__ float sm[];
    float* Ws = sm;                               // 96*98 floats (current tap, padded)
    unsigned int* Mh = (unsigned int*)(sm + 96*WPAD);  // 4*58*3 u32
    int tb = blockIdx.y, rt = blockIdx.x, tid = threadIdx.x;
    int h0 = rt*2;
    const unsigned int* Mp = Msk + (size_t)tb*Ln*3;

    for (int i = tid; i < MROWS*MCOLS*3; i += 256){
        int r = i / (MCOLS*3);
        int rem = i - r*(MCOLS*3);
        int c = rem / 3, w = rem - c*3;
        int h = h0 - 1 + r;
        int ww = c - 1;
        unsigned int v = 0u;
        if (h >= 0 && h < 56 && ww >= 0 && ww < 56)
            v = Mp[((size_t)h*56 + ww)*3 + w];
        Mh[i] = v;
    }

    int tx = tid & 15, ty = tid >> 4;
    int co0 = ty*6;
    int pbase[7];
    #pragma unroll
    for (int j = 0; j < 7; j++){
        int lp = tx*7 + j;                 // 0..111
        int ro = lp / 56, w = lp - ro*56;
        pbase[j] = ((ro+1)*MCOLS + (w+1))*3;
    }
    float acc[6][7];
    #pragma unroll
    for (int i = 0; i < 6; i++)
        #pragma unroll
        for (int j = 0; j < 7; j++) acc[i][j] = 0.f;

    for (int tap = 0; tap < 9; tap++){
        __syncthreads();
        const float* wp = Wt + tap*9216;
        for (int i = tid; i < 9216; i += 256){
            int k = i / 96, co = i - k*96;
            Ws[k*WPAD + co] = wp[i];
        }
        __syncthreads();
        int dy = tap/3 - 1;
        int dx = tap - (tap/3)*3 - 1;
        int toff = (dy*MCOLS + dx)*3;

        #pragma unroll
        for (int j = 0; j < 7; j++){
            const unsigned int* mp = Mh + pbase[j] + toff;
            #pragma unroll
            for (int w3 = 0; w3 < 3; w3++){
                unsigned int m = mp[w3];
                while (m){
                    int b = __ffs(m) - 1;
                    m &= (m - 1u);
                    int k = w3*32 + b;
                    const float2* rp = (const float2*)(Ws + k*WPAD + co0);
                    float2 w01 = rp[0], w23 = rp[1], w45 = rp[2];
                    acc[0][j] += w01.x;
                    acc[1][j] += w01.y;
                    acc[2][j] += w23.x;
                    acc[3][j] += w23.y;
                    acc[4][j] += w45.x;
                    acc[5][j] += w45.y;
                }
            }
        }
    }
    int l0 = h0*56;
    #pragma unroll
    for (int i = 0; i < 6; i++){
        int co = co0 + i;
        float bv = bias[co];
        float* yp = Y + (size_t)tb*PLANE + (size_t)co*Ln + l0 + tx*7;
        #pragma unroll
        for (int j = 0; j < 7; j++)
            yp[j] = siluf(acc[i][j] + bv);
    }
}

// ---------------- fused depthwise 3x3 conv + silu + dual (normal/transposed) write ---------
__global__ void __launch_bounds__(256) dwconvt_kernel(
    const float* __restrict__ X, const float* __restrict__ Wd,
    float* __restrict__ Xe, float* __restrict__ XeT)
{
    __shared__ float s[Ln];
    __shared__ float o[Ln];
    int p = blockIdx.x;                 // tb*96 + d
    int d = p % 96;
    const float* xp = X + (size_t)p*Ln;
    int tid = threadIdx.x;
    for (int i = tid; i < Ln; i += 256) s[i] = xp[i];
    float w[9];
    #pragma unroll
    for (int j = 0; j < 9; j++) w[j] = Wd[d*9 + j];
    __syncthreads();
    for (int i = tid; i < Ln; i += 256){
        int h = i / 56, ww = i - h*56;
        float a = 0.f;
        #pragma unroll
        for (int dy = -1; dy <= 1; dy++){
            int hh = h + dy;
            if (hh < 0 || hh >= 56) continue;
            #pragma unroll
            for (int dx = -1; dx <= 1; dx++){
                int cc = ww + dx;
                if (cc < 0 || cc >= 56) continue;
                a = fmaf(w[(dy+1)*3 + (dx+1)], s[hh*56 + cc], a);
            }
        }
        o[i] = siluf(a);
    }
    __syncthreads();
    float* ye = Xe + (size_t)p*Ln;
    float* yt = XeT + (size_t)p*Ln;
    for (int i = tid; i < Ln; i += 256){
        ye[i] = o[i];
        int a = i / 56, b = i - a*56;
        yt[i] = o[b*56 + a];
    }
}

// ---------------- dbl projection v2: 112 threads, one l/thread, [d][k][r] weights ----------
__global__ void __launch_bounds__(112) projdbl_kernel(
    const float* __restrict__ Xe, const float* __restrict__ XeT,
    const float* __restrict__ Wp, float* __restrict__ Dbl)
{
    __shared__ float sw[3072];          // [d][k][r]: sw[d*32 + k*8 + r]
    int tb = blockIdx.y, lt = blockIdx.x, tid = threadIdx.x;
    for (int i = tid; i < 3072; i += 112){
        int d = i >> 5, rem = i & 31;
        int k = rem >> 3, r = rem & 7;
        sw[i] = Wp[k*768 + r*96 + d];
    }
    __syncthreads();

    int l = lt*112 + tid;
    const float* xe = Xe + (size_t)tb*PLANE + l;
    const float* xt = XeT + (size_t)tb*PLANE + l;

    float a0[8], a1[8], a2[8], a3[8];
    #pragma unroll
    for (int r = 0; r < 8; r++){ a0[r]=0.f; a1[r]=0.f; a2[r]=0.f; a3[r]=0.f; }

    #pragma unroll 2
    for (int d = 0; d < 96; d++){
        float ev = xe[(size_t)d*Ln];
        float tv = xt[(size_t)d*Ln];
        const float2* wd = (const float2*)(sw + d*32);
        #pragma unroll
        for (int r2 = 0; r2 < 4; r2++){
            float2 p0 = wd[r2];
            float2 p1 = wd[4 + r2];
            float2 p2 = wd[8 + r2];
            float2 p3 = wd[12 + r2];
            a0[r2*2]   = fmaf(ev, p0.x, a0[r2*2]);
            a0[r2*2+1] = fmaf(ev, p0.y, a0[r2*2+1]);
            a1[r2*2]   = fmaf(tv, p1.x, a1[r2*2]);
            a1[r2*2+1] = fmaf(tv, p1.y, a1[r2*2+1]);
            a2[r2*2]   = fmaf(ev, p2.x, a2[r2*2]);
            a2[r2*2+1] = fmaf(ev, p2.y, a2[r2*2+1]);
            a3[r2*2]   = fmaf(tv, p3.x, a3[r2*2]);
            a3[r2*2+1] = fmaf(tv, p3.y, a3[r2*2+1]);
        }
    }
    int lr = Ln - 1 - l;
    size_t o0 = ((size_t)(tb*4+0)*Ln + l )*8;
    size_t o1 = ((size_t)(tb*4+1)*Ln + l )*8;
    size_t o2 = ((size_t)(tb*4+2)*Ln + lr)*8;
    size_t o3 = ((size_t)(tb*4+3)*Ln + lr)*8;
    *(float4*)(Dbl+o0)   = make_float4(a0[0],a0[1],a0[2],a0[3]);
    *(float4*)(Dbl+o0+4) = make_float4(a0[4],a0[5],a0[6],a0[7]);
    *(float4*)(Dbl+o1)   = make_float4(a1[0],a1[1],a1[2],a1[3]);
    *(float4*)(Dbl+o1+4) = make_float4(a1[4],a1[5],a1[6],a1[7]);
    *(float4*)(Dbl+o2)   = make_float4(a2[0],a2[1],a2[2],a2[3]);
    *(float4*)(Dbl+o2+4) = make_float4(a2[4],a2[5],a2[6],a2[7]);
    *(float4*)(Dbl+o3)   = make_float4(a3[0],a3[1],a3[2],a3[3]);
    *(float4*)(Dbl+o3+4) = make_float4(a3[4],a3[5],a3[6],a3[7]);
}

// ---------------- fused scan + direction combine ----------------
// block = (pairsel, d-pair, tb): 4 warps scan (k, k+2) x (d0, d1) rows into skewed smem,
// then combine ysk[l] + rev(ysk2)[l] (pairsel=0 -> Ya; pairsel=1 -> transposed T1T)
__global__ void __launch_bounds__(128) scanc_kernel(
    const float* __restrict__ Xe, const float* __restrict__ XeT,
    const float* __restrict__ Dbl,
    const float* __restrict__ DtW, const float* __restrict__ DtB,
    const float* __restrict__ Alog, const float* __restrict__ DsP,
    float* __restrict__ Ya, float* __restrict__ T1T)
{
    __shared__ float s[4*SROW];
    int tid = threadIdx.x;
    int warp = tid >> 5, lane = tid & 31;
    int bx = blockIdx.x;
    int pairsel = bx / 48;              // 0: dirs {0,2}; 1: dirs {1,3}
    int dp = bx - pairsel*48;           // d-pair index
    int tb = blockIdx.y;
    int k = pairsel + ((warp >= 2) ? 2 : 0);
    int d = dp*2 + (warp & 1);
    int kd = k*96 + d;

    float w0 = DtW[kd*6+0], w1 = DtW[kd*6+1], w2 = DtW[kd*6+2];
    float w3 = DtW[kd*6+3], w4 = DtW[kd*6+4], w5 = DtW[kd*6+5];
    float bdt = DtB[kd];
    float A   = -expf(Alog[kd]);
    float Dv  = DsP[kd];
    const float* xrow = ((k & 1) ? XeT : Xe) + (size_t)(tb*96 + d)*Ln;
    const float* dp_p = Dbl + (size_t)(tb*4 + k)*Ln*8;
    bool rev = (k >= 2);
    float* srow = s + warp*SROW;

    float carry = 0.f;
    for (int j = 0; j < 98; j++){
        int l = j*32 + lane;
        float4 p0 = *(const float4*)(dp_p + (size_t)l*8);
        float4 p1 = *(const float4*)(dp_p + (size_t)l*8 + 4);
        float dtr = bdt + p0.x*w0 + p0.y*w1 + p0.z*w2 + p0.w*w3 + p1.x*w4 + p1.y*w5;
        float sp  = softplus_fast(dtr);
        float da  = __expf(sp * A);
        float xsv = xrow[rev ? (Ln-1-l) : l];
        float db  = sp * p1.z * xsv;

        float Ai = da, Bi = db;
        #pragma unroll
        for (int ofs = 1; ofs < 32; ofs <<= 1){
            float aL = __shfl_up_sync(0xffffffffu, Ai, ofs);
            float bL = __shfl_up_sync(0xffffffffu, Bi, ofs);
            if (lane >= ofs){ Bi = fmaf(bL, Ai, Bi); Ai *= aL; }
        }
        float h = fmaf(Ai, carry, Bi);
        carry = __shfl_sync(0xffffffffu, h, 31);
        srow[l + l/56] = fmaf(p1.w, h, Dv * xsv);
    }
    __syncthreads();

    // combine: warps cooperate over both d rows
    if (pairsel == 0){
        #pragma unroll
        for (int dd = 0; dd < 2; dd++){
            const float* sa = s + dd*SROW;         // k = 0 row
            const float* sb = s + (2+dd)*SROW;     // k = 2 row
            float* outp = Ya + ((size_t)(tb*96 + dp*2 + dd))*Ln;
            for (int i = tid; i < Ln; i += 128){
                int ir = Ln - 1 - i;
                outp[i] = sa[i + i/56] + sb[ir + ir/56];
            }
        }
    } else {
        #pragma unroll
        for (int dd = 0; dd < 2; dd++){
            const float* sa = s + dd*SROW;         // k = 1 row
            const float* sb = s + (2+dd)*SROW;     // k = 3 row
            float* outp = T1T + ((size_t)(tb*96 + dp*2 + dd))*Ln;
            for (int i = tid; i < Ln; i += 128){
                int h = i / 56, w = i - h*56;
                int T  = w*56 + h;
                int Tr = Ln - 1 - T;
                outp[i] = sa[T + w] + sb[Tr + Tr/56];
            }
        }
    }
}

// ---------------- fused: (Ya + T1T) + LayerNorm + out_proj GEMM ----------------
__global__ void __launch_bounds__(256) comblnproj_kernel(
    const float* __restrict__ Ya, const float* __restrict__ T1T,
    const float* __restrict__ g, const float* __restrict__ bn,
    const float* __restrict__ Wo, float* __restrict__ Out)
{
    extern __shared__ float sm[];
    float* s    = sm;                   // 96*64
    float* Ws   = sm + 96*64;           // 96*98 [k][co]
    float* part = Ws + 96*GSTR;         // 8*64
    float* smu  = part + 512;           // 64
    float* srs  = smu + 64;             // 64
    int b = blockIdx.y, lt = blockIdx.x, tid = threadIdx.x;
    int l0 = lt*64;

    for (int i = tid; i < 96*64; i += 256){
        int dd = i >> 6, j = i & 63;
        size_t gix = ((size_t)(b*96 + dd))*Ln + l0 + j;
        s[i] = Ya[gix] + T1T[gix];
    }
    for (int i = tid; i < 96*96; i += 256){
        int co = i / 96, k = i - co*96;
        Ws[k*GSTR + co] = Wo[i];
    }
    __syncthreads();
    {
        int pr = tid >> 6, j = tid & 63;
        float su = 0.f, sq = 0.f;
        for (int dd = pr*24; dd < pr*24 + 24; dd++){
            float v = s[dd*64 + j];
            su += v; sq = fmaf(v, v, sq);
        }
        part[pr*64 + j] = su;
        part[256 + pr*64 + j] = sq;
    }
    __syncthreads();
    if (tid < 64){
        float su = part[tid] + part[64+tid] + part[128+tid] + part[192+tid];
        float sq = part[256+tid] + part[320+tid] + part[384+tid] + part[448+tid];
        float mu = su * (1.f/96.f);
        float var = sq * (1.f/96.f) - mu*mu;
        smu[tid] = mu;
        srs[tid] = rsqrtf(var + 1e-5f);
    }
    __syncthreads();
    for (int i = tid; i < 96*64; i += 256){
        int dd = i >> 6, j = i & 63;
        s[i] = (s[i] - smu[j]) * srs[j] * g[dd] + bn[dd];
    }
    __syncthreads();

    int tx = tid & 15, ty = tid >> 4;
    unsigned long long acc[6][2];
    #pragma unroll
    for (int i = 0; i < 6; i++){ acc[i][0] = 0ull; acc[i][1] = 0ull; }
    #pragma unroll 4
    for (int k = 0; k < 96; k++){
        float4 a = *(const float4*)(s + k*64 + tx*4);
        unsigned long long x01 = pack2(a.x, a.y);
        unsigned long long x23 = pack2(a.z, a.w);
        const float2* wrow = (const float2*)(Ws + k*GSTR + ty*6);
        float2 w01 = wrow[0], w23 = wrow[1], w45 = wrow[2];
        float wv[6] = {w01.x, w01.y, w23.x, w23.y, w45.x, w45.y};
        #pragma unroll
        for (int i = 0; i < 6; i++){
            unsigned long long ww = pack2(wv[i], wv[i]);
            FMA2(acc[i][0], ww, x01);
            FMA2(acc[i][1], ww, x23);
        }
    }
    #pragma unroll
    for (int i = 0; i < 6; i++){
        int co = ty*6 + i;
        float o0, o1, o2, o3;
        unpack2(acc[i][0], o0, o1);
        unpack2(acc[i][1], o2, o3);
        float* yp = Out + (size_t)b*PLANE + (size_t)co*Ln + l0 + tx*4;
        *(float4*)yp = make_float4(o0, o1, o2, o3);
    }
}

// ---------------- final LIF over T=4 and multiply by input x ----------------
__global__ void lif4_kernel(const float* __restrict__ Z, const float* __restrict__ X0,
                            float* __restrict__ Out){
    const int N = BB*PLANE;           // 1204224
    int i = blockIdx.x*blockDim.x + threadIdx.x;
    if (i >= N) return;
    float v = 0.f;
    #pragma unroll
    for (int t = 0; t < TT; t++){
        size_t idx = (size_t)t*N + i;
        float x = Z[idx];
        v += (x - v) * 0.5f;
        float sgn = (v >= 1.f) ? 1.f : 0.f;
        Out[idx] = sgn * X0[idx];
        v = (sgn > 0.f) ? 0.f : v;
    }
}

// ---------------- host launcher ----------------
extern "C" void kernel_launch(void* const* d_in, const int* in_sizes, int n_in,
                              void* d_out, int out_size)
{
    const float* x          = (const float*)d_in[0];
    const float* in_proj_w  = (const float*)d_in[1];
    const float* in_proj_b  = (const float*)d_in[2];
    const float* conv_w     = (const float*)d_in[3];
    const float* conv_b     = (const float*)d_in[4];
    const float* ssm_in_w   = (const float*)d_in[5];
    const float* ssm_conv_w = (const float*)d_in[6];
    const float* x_proj_w   = (const float*)d_in[7];
    const float* dt_proj_w  = (const float*)d_in[8];
    const float* dt_proj_b  = (const float*)d_in[9];
    const float* A_logs     = (const float*)d_in[10];
    const float* Ds         = (const float*)d_in[11];
    const float* ln_g       = (const float*)d_in[12];
    const float* ln_b       = (const float*)d_in[13];
    const float* out_proj_w = (const float*)d_in[14];
    float* out = (float*)d_out;

    float *bufA, *bufB, *bufT, *dbl, *ya, *t1t, *wc;
    unsigned int* msk;
    cudaGetSymbolAddress((void**)&bufA, g_bufA);
    cudaGetSymbolAddress((void**)&bufB, g_bufB);
    cudaGetSymbolAddress((void**)&bufT, g_bufT);
    cudaGetSymbolAddress((void**)&dbl,  g_dbl);
    cudaGetSymbolAddress((void**)&ya,   g_ya);
    cudaGetSymbolAddress((void**)&t1t,  g_t1t);
    cudaGetSymbolAddress((void**)&wc,   g_wc);
    cudaGetSymbolAddress((void**)&msk,  g_msk);

    const int GEMM_SMEM = (96*GSTR + 96*64)*4;                  // 62208
    const int CONV_SMEM = 96*WPAD*4 + MROWS*MCOLS*3*4;          // 40416
    const int CLNP_SMEM = (96*64 + 96*GSTR + 512 + 128)*4;      // 64768
    cudaFuncSetAttribute(pw_gemm_kernel,    cudaFuncAttributeMaxDynamicSharedMemorySize, GEMM_SMEM);
    cudaFuncSetAttribute(conv3x3_kernel,    cudaFuncAttributeMaxDynamicSharedMemorySize, CONV_SMEM);
    cudaFuncSetAttribute(comblnproj_kernel, cudaFuncAttributeMaxDynamicSharedMemorySize, CLNP_SMEM);

    // 0. reorder conv weights
    wreorder_kernel<<<(9*96*96 + 255)/256, 256>>>(conv_w, wc);
    // 1. in_proj (+bias) -> bufA
    pw_gemm_kernel<<<dim3(49,16), 256, GEMM_SMEM>>>(x, in_proj_w, in_proj_b, bufA);
    // 2. LIF over 16 steps -> bitmasks
    lif16_kernel<<<(Ln*3 + 255)/256, 256>>>(bufA, msk);
    // 3. sparse full 3x3 conv + bias + silu -> bufA
    conv3x3_kernel<<<dim3(28,16), 256, CONV_SMEM>>>(msk, wc, conv_b, bufA);
    // 4. ssm_in pointwise -> bufB
    pw_gemm_kernel<<<dim3(49,16), 256, GEMM_SMEM>>>(bufA, ssm_in_w, (const float*)nullptr, bufB);
    // 5+6. fused depthwise conv + silu -> bufA (= xe) and transposed -> bufT (= xeT)
    dwconvt_kernel<<<TBn*Cn, 256>>>(bufB, ssm_conv_w, bufA, bufT);
    // 7. x_proj for all 4 directions -> dbl
    projdbl_kernel<<<dim3(28,16), 112>>>(bufA, bufT, x_proj_w, dbl);
    // 8. fused selective scan + direction combine -> ya, t1t
    scanc_kernel<<<dim3(96,16), 128>>>(bufA, bufT, dbl, dt_proj_w, dt_proj_b, A_logs, Ds, ya, t1t);
    // 9. (Ya + T1T) + LayerNorm + out_proj fused -> bufB
    comblnproj_kernel<<<dim3(49,16), 256, CLNP_SMEM>>>(ya, t1t, ln_g, ln_b, out_proj_w, bufB);
    // 10. final LIF(T=4) * x -> out
    lif4_kernel<<<(BB*PLANE + 255)/256, 256>>>(bufB, x, out);
}

// round 16
// speedup vs baseline: 1.0058x; 1.0058x over previous
#include <cuda_runtime.h>
#include <math.h>

#define TT 4
#define BB 4
#define TBn 16
#define Cn 96
#define Hn 56
#define Wn 56
#define Ln 3136
#define PLANE (Cn*Ln)          /* 301056 */
#define TOT (TBn*Cn*Ln)        /* 4816896 */

// ---------------- scratch (device globals; no allocation) ----------------
__device__ float g_bufA[TOT];
__device__ float g_bufB[TOT];
__device__ float g_bufT[TOT];
__device__ float g_dbl[TBn*4*Ln*8];     // (tb,k,l,8)
__device__ float g_ys[TBn*4*Cn*Ln];     // (tb,k,d,l) 77MB
__device__ float g_wc[9*Cn*Cn];         // conv weights reordered [tap][ci][co]
__device__ float g_wt[3*Cn*Cn];         // gemm weights transposed [m][k][co]
__device__ unsigned int g_msk[TBn*Ln*3];// spike bitmasks: [tb][l][3 words of 32 ch]

// ---------------- helpers ----------------
__device__ __forceinline__ float softplus_fast(float x){
    return (x > 15.f) ? x : __logf(1.f + __expf(x));
}
__device__ __forceinline__ float siluf(float v){
    return v * (1.f / (1.f + expf(-v)));
}

// packed fp32x2 helpers (Blackwell — elementwise IEEE fp32, 2 lanes/instr)
__device__ __forceinline__ unsigned long long pack2(float lo, float hi){
    unsigned long long r;
    asm("mov.b64 %0, {%1, %2};" : "=l"(r) : "r"(__float_as_uint(lo)), "r"(__float_as_uint(hi)));
    return r;
}
__device__ __forceinline__ void unpack2(unsigned long long v, float& lo, float& hi){
    unsigned int a, b;
    asm("mov.b64 {%0, %1}, %2;" : "=r"(a), "=r"(b) : "l"(v));
    lo = __uint_as_float(a); hi = __uint_as_float(b);
}
#define FMA2(acc, a, b) asm("fma.rn.f32x2 %0, %1, %2, %0;" : "+l"(acc) : "l"(a), "l"(b))

// ---------------- conv weight reorder: (co,ci,ky,kx) -> [tap][ci][co] ----------------
__global__ void wreorder_kernel(const float* __restrict__ Win, float* __restrict__ Wt){
    int i = blockIdx.x*blockDim.x + threadIdx.x;
    if (i >= 9*96*96) return;
    int tap = i % 9;
    int ci  = (i / 9) % 96;
    int co  = i / (9*96);
    Wt[tap*9216 + ci*96 + co] = Win[i];
}

// ---------------- gemm weight transpose: W[co][ci] -> Wt[m][ci][co] ----------------
__global__ void wtrans_kernel(const float* __restrict__ W0, const float* __restrict__ W1,
                              const float* __restrict__ W2, float* __restrict__ Wt){
    int i = blockIdx.x*blockDim.x + threadIdx.x;
    if (i >= 3*9216) return;
    int m = i / 9216;
    int r = i - m*9216;
    int k = r / 96, co = r - k*96;
    const float* Wm = (m == 0) ? W0 : ((m == 1) ? W1 : W2);
    Wt[i] = Wm[co*96 + k];
}

// ---------------- pointwise 96x96 GEMM: weights straight from L1 (pre-transposed [k][co]) --
__global__ void __launch_bounds__(256) pw_gemm_kernel(
    const float* __restrict__ X, const float* __restrict__ Wt,
    const float* __restrict__ bias, float* __restrict__ Y)
{
    __shared__ float Xs[96*64];
    int tb = blockIdx.y;
    int lt = blockIdx.x;
    int tid = threadIdx.x;

    const float* Xp = X + (size_t)tb*PLANE + lt*64;
    for (int i = tid; i < 96*64; i += 256){
        int k = i >> 6, j = i & 63;
        Xs[i] = Xp[(size_t)k*Ln + j];
    }
    __syncthreads();

    int tx = tid & 15, ty = tid >> 4;
    unsigned long long acc[6][2];
    #pragma unroll
    for (int i = 0; i < 6; i++){ acc[i][0] = 0ull; acc[i][1] = 0ull; }

    #pragma unroll 4
    for (int k = 0; k < 96; k++){
        float4 a = *(const float4*)(Xs + k*64 + tx*4);
        unsigned long long x01 = pack2(a.x, a.y);
        unsigned long long x23 = pack2(a.z, a.w);
        const float2* wrow = (const float2*)(Wt + k*96 + ty*6);
        float2 w01 = __ldg(wrow), w23 = __ldg(wrow+1), w45 = __ldg(wrow+2);
        float wv[6] = {w01.x, w01.y, w23.x, w23.y, w45.x, w45.y};
        #pragma unroll
        for (int i = 0; i < 6; i++){
            unsigned long long ww = pack2(wv[i], wv[i]);
            FMA2(acc[i][0], ww, x01);
            FMA2(acc[i][1], ww, x23);
        }
    }
    #pragma unroll
    for (int i = 0; i < 6; i++){
        int co = ty*6 + i;
        float bv = bias ? bias[co] : 0.f;
        float o0, o1, o2, o3;
        unpack2(acc[i][0], o0, o1);
        unpack2(acc[i][1], o2, o3);
        float* yp = Y + (size_t)tb*PLANE + (size_t)co*Ln + lt*64 + tx*4;
        *(float4*)yp = make_float4(o0+bv, o1+bv, o2+bv, o3+bv);
    }
}

// ---------------- LIF over 16 steps -> channel bitmasks ----------------
__global__ void lif16_kernel(const float* __restrict__ X, unsigned int* __restrict__ M){
    int tid = blockIdx.x*blockDim.x + threadIdx.x;
    if (tid >= Ln*3) return;
    int w3 = tid / Ln;
    int l  = tid - w3*Ln;
    float v[32];
    #pragma unroll
    for (int c = 0; c < 32; c++) v[c] = 0.f;
    for (int t = 0; t < TBn; t++){
        unsigned int m = 0u;
        #pragma unroll
        for (int c = 0; c < 32; c++){
            float x = X[((size_t)t*Cn + w3*32 + c)*Ln + l];
            v[c] += (x - v[c]) * 0.5f;
            bool s = (v[c] >= 1.0f);
            if (s) m |= (1u << c);
            v[c] = s ? 0.f : v[c];
        }
        M[((size_t)t*Ln + l)*3 + w3] = m;
    }
}

// ---------------- sparse full 3x3 conv (R10 proven config) ----------------
#define MROWS 4
#define MCOLS 58
#define WPAD 98
__global__ void __launch_bounds__(256, 3) conv3x3_kernel(
    const unsigned int* __restrict__ Msk, const float* __restrict__ Wt,
    const float* __restrict__ bias, float* __restrict__ Y)
{
    extern __shared__ float sm[];
    float* Ws = sm;                               // 96*98 floats (current tap, padded)
    unsigned int* Mh = (unsigned int*)(sm + 96*WPAD);  // 4*58*3 u32
    int tb = blockIdx.y, rt = blockIdx.x, tid = threadIdx.x;
    int h0 = rt*2;
    const unsigned int* Mp = Msk + (size_t)tb*Ln*3;

    for (int i = tid; i < MROWS*MCOLS*3; i += 256){
        int r = i / (MCOLS*3);
        int rem = i - r*(MCOLS*3);
        int c = rem / 3, w = rem - c*3;
        int h = h0 - 1 + r;
        int ww = c - 1;
        unsigned int v = 0u;
        if (h >= 0 && h < 56 && ww >= 0 && ww < 56)
            v = Mp[((size_t)h*56 + ww)*3 + w];
        Mh[i] = v;
    }

    int tx = tid & 15, ty = tid >> 4;
    int co0 = ty*6;
    int pbase[7];
    #pragma unroll
    for (int j = 0; j < 7; j++){
        int lp = tx*7 + j;                 // 0..111
        int ro = lp / 56, w = lp - ro*56;
        pbase[j] = ((ro+1)*MCOLS + (w+1))*3;
    }
    float acc[6][7];
    #pragma unroll
    for (int i = 0; i < 6; i++)
        #pragma unroll
        for (int j = 0; j < 7; j++) acc[i][j] = 0.f;

    for (int tap = 0; tap < 9; tap++){
        __syncthreads();
        const float* wp = Wt + tap*9216;
        for (int i = tid; i < 9216; i += 256){
            int k = i / 96, co = i - k*96;
            Ws[k*WPAD + co] = wp[i];
        }
        __syncthreads();
        int dy = tap/3 - 1;
        int dx = tap - (tap/3)*3 - 1;
        int toff = (dy*MCOLS + dx)*3;

        #pragma unroll
        for (int j = 0; j < 7; j++){
            const unsigned int* mp = Mh + pbase[j] + toff;
            #pragma unroll
            for (int w3 = 0; w3 < 3; w3++){
                unsigned int m = mp[w3];
                while (m){
                    int b = __ffs(m) - 1;
                    m &= (m - 1u);
                    int k = w3*32 + b;
                    const float2* rp = (const float2*)(Ws + k*WPAD + co0);
                    float2 w01 = rp[0], w23 = rp[1], w45 = rp[2];
                    acc[0][j] += w01.x;
                    acc[1][j] += w01.y;
                    acc[2][j] += w23.x;
                    acc[3][j] += w23.y;
                    acc[4][j] += w45.x;
                    acc[5][j] += w45.y;
                }
            }
        }
    }
    int l0 = h0*56;
    #pragma unroll
    for (int i = 0; i < 6; i++){
        int co = co0 + i;
        float bv = bias[co];
        float* yp = Y + (size_t)tb*PLANE + (size_t)co*Ln + l0 + tx*7;
        #pragma unroll
        for (int j = 0; j < 7; j++)
            yp[j] = siluf(acc[i][j] + bv);
    }
}

// ---------------- fused depthwise 3x3 conv + silu + dual (normal/transposed) write ---------
__global__ void __launch_bounds__(256) dwconvt_kernel(
    const float* __restrict__ X, const float* __restrict__ Wd,
    float* __restrict__ Xe, float* __restrict__ XeT)
{
    __shared__ float s[Ln];
    __shared__ float o[Ln];
    int p = blockIdx.x;                 // tb*96 + d
    int d = p % 96;
    const float* xp = X + (size_t)p*Ln;
    int tid = threadIdx.x;
    for (int i = tid; i < Ln; i += 256) s[i] = xp[i];
    float w[9];
    #pragma unroll
    for (int j = 0; j < 9; j++) w[j] = Wd[d*9 + j];
    __syncthreads();
    for (int i = tid; i < Ln; i += 256){
        int h = i / 56, ww = i - h*56;
        float a = 0.f;
        #pragma unroll
        for (int dy = -1; dy <= 1; dy++){
            int hh = h + dy;
            if (hh < 0 || hh >= 56) continue;
            #pragma unroll
            for (int dx = -1; dx <= 1; dx++){
                int cc = ww + dx;
                if (cc < 0 || cc >= 56) continue;
                a = fmaf(w[(dy+1)*3 + (dx+1)], s[hh*56 + cc], a);
            }
        }
        o[i] = siluf(a);
    }
    __syncthreads();
    float* ye = Xe + (size_t)p*Ln;
    float* yt = XeT + (size_t)p*Ln;
    for (int i = tid; i < Ln; i += 256){
        ye[i] = o[i];
        int a = i / 56, b = i - a*56;
        yt[i] = o[b*56 + a];
    }
}

// ---------------- fused (ys1 + rev(ys3)) then transpose ----------------
__global__ void comb1t_kernel(const float* __restrict__ Ys, float* __restrict__ T1T){
    __shared__ float s[Ln];
    int p = blockIdx.x;                 // (tb*96 + d)
    int tb = p / 96, d = p - tb*96;
    const float* y1 = Ys + ((size_t)(tb*4+1)*96 + d)*Ln;
    const float* y3 = Ys + ((size_t)(tb*4+3)*96 + d)*Ln;
    float* yp = T1T + (size_t)p*Ln;
    for (int i = threadIdx.x; i < Ln; i += blockDim.x)
        s[i] = y1[i] + y3[Ln-1-i];
    __syncthreads();
    for (int i = threadIdx.x; i < Ln; i += blockDim.x){
        int a = i / 56, b = i - a*56;
        yp[i] = s[b*56 + a];
    }
}

// ---------------- dbl projection v2: 112 threads, one l/thread, [d][k][r] weights ----------
__global__ void __launch_bounds__(112) projdbl_kernel(
    const float* __restrict__ Xe, const float* __restrict__ XeT,
    const float* __restrict__ Wp, float* __restrict__ Dbl)
{
    __shared__ float sw[3072];          // [d][k][r]: sw[d*32 + k*8 + r]
    int tb = blockIdx.y, lt = blockIdx.x, tid = threadIdx.x;
    for (int i = tid; i < 3072; i += 112){
        int d = i >> 5, rem = i & 31;
        int k = rem >> 3, r = rem & 7;
        sw[i] = Wp[k*768 + r*96 + d];
    }
    __syncthreads();

    int l = lt*112 + tid;
    const float* xe = Xe + (size_t)tb*PLANE + l;
    const float* xt = XeT + (size_t)tb*PLANE + l;

    float a0[8], a1[8], a2[8], a3[8];
    #pragma unroll
    for (int r = 0; r < 8; r++){ a0[r]=0.f; a1[r]=0.f; a2[r]=0.f; a3[r]=0.f; }

    #pragma unroll 2
    for (int d = 0; d < 96; d++){
        float ev = xe[(size_t)d*Ln];
        float tv = xt[(size_t)d*Ln];
        const float2* wd = (const float2*)(sw + d*32);
        #pragma unroll
        for (int r2 = 0; r2 < 4; r2++){
            float2 p0 = wd[r2];
            float2 p1 = wd[4 + r2];
            float2 p2 = wd[8 + r2];
            float2 p3 = wd[12 + r2];
            a0[r2*2]   = fmaf(ev, p0.x, a0[r2*2]);
            a0[r2*2+1] = fmaf(ev, p0.y, a0[r2*2+1]);
            a1[r2*2]   = fmaf(tv, p1.x, a1[r2*2]);
            a1[r2*2+1] = fmaf(tv, p1.y, a1[r2*2+1]);
            a2[r2*2]   = fmaf(ev, p2.x, a2[r2*2]);
            a2[r2*2+1] = fmaf(ev, p2.y, a2[r2*2+1]);
            a3[r2*2]   = fmaf(tv, p3.x, a3[r2*2]);
            a3[r2*2+1] = fmaf(tv, p3.y, a3[r2*2+1]);
        }
    }
    int lr = Ln - 1 - l;
    size_t o0 = ((size_t)(tb*4+0)*Ln + l )*8;
    size_t o1 = ((size_t)(tb*4+1)*Ln + l )*8;
    size_t o2 = ((size_t)(tb*4+2)*Ln + lr)*8;
    size_t o3 = ((size_t)(tb*4+3)*Ln + lr)*8;
    *(float4*)(Dbl+o0)   = make_float4(a0[0],a0[1],a0[2],a0[3]);
    *(float4*)(Dbl+o0+4) = make_float4(a0[4],a0[5],a0[6],a0[7]);
    *(float4*)(Dbl+o1)   = make_float4(a1[0],a1[1],a1[2],a1[3]);
    *(float4*)(Dbl+o1+4) = make_float4(a1[4],a1[5],a1[6],a1[7]);
    *(float4*)(Dbl+o2)   = make_float4(a2[0],a2[1],a2[2],a2[3]);
    *(float4*)(Dbl+o2+4) = make_float4(a2[4],a2[5],a2[6],a2[7]);
    *(float4*)(Dbl+o3)   = make_float4(a3[0],a3[1],a3[2],a3[3]);
    *(float4*)(Dbl+o3+4) = make_float4(a3[4],a3[5],a3[6],a3[7]);
}

// ---------------- fused selective scan: warp scans 2 d-rows, sharing dbl loads -------------
__global__ void __launch_bounds__(128) scan_kernel(
    const float* __restrict__ Xe, const float* __restrict__ XeT,
    const float* __restrict__ Dbl,
    const float* __restrict__ DtW, const float* __restrict__ DtB,
    const float* __restrict__ Alog, const float* __restrict__ DsP,
    float* __restrict__ Ys)
{
    int warp = threadIdx.x >> 5, lane = threadIdx.x & 31;
    int bid = blockIdx.x;                 // 64*12 blocks
    int bk = bid / 12;                    // tb*4+k
    int dg = bid - bk*12;                 // 0..11
    int d0 = dg*8 + warp*2;               // this warp: d0, d0+1
    int b  = bk >> 2, k = bk & 3;
    int kd0 = k*96 + d0;
    int kd1 = kd0 + 1;

    float u0 = DtW[kd0*6+0], u1 = DtW[kd0*6+1], u2 = DtW[kd0*6+2];
    float u3 = DtW[kd0*6+3], u4 = DtW[kd0*6+4], u5 = DtW[kd0*6+5];
    float v0 = DtW[kd1*6+0], v1 = DtW[kd1*6+1], v2 = DtW[kd1*6+2];
    float v3 = DtW[kd1*6+3], v4 = DtW[kd1*6+4], v5 = DtW[kd1*6+5];
    float bdt0 = DtB[kd0], bdt1 = DtB[kd1];
    float A0 = -expf(Alog[kd0]), A1 = -expf(Alog[kd1]);
    float Dv0 = DsP[kd0], Dv1 = DsP[kd1];

    const float* xbase = ((k & 1) ? XeT : Xe) + (size_t)(b*96 + d0)*Ln;
    const float* xrow0 = xbase;
    const float* xrow1 = xbase + Ln;
    const float* dp = Dbl + (size_t)bk*Ln*8;
    float* yrow0 = Ys + ((size_t)bk*96 + d0)*Ln;
    float* yrow1 = yrow0 + Ln;
    bool rev = (k >= 2);

    float carry0 = 0.f, carry1 = 0.f;
    for (int j = 0; j < 98; j++){
        int l = j*32 + lane;
        float4 p0 = *(const float4*)(dp + (size_t)l*8);
        float4 p1 = *(const float4*)(dp + (size_t)l*8 + 4);
        int lx = rev ? (Ln-1-l) : l;
        float xs0 = xrow0[lx];
        float xs1 = xrow1[lx];

        float dtr0 = bdt0 + p0.x*u0 + p0.y*u1 + p0.z*u2 + p0.w*u3 + p1.x*u4 + p1.y*u5;
        float dtr1 = bdt1 + p0.x*v0 + p0.y*v1 + p0.z*v2 + p0.w*v3 + p1.x*v4 + p1.y*v5;
        float sp0 = softplus_fast(dtr0);
        float sp1 = softplus_fast(dtr1);
        float da0 = __expf(sp0 * A0);
        float da1 = __expf(sp1 * A1);
        float db0 = sp0 * p1.z * xs0;
        float db1 = sp1 * p1.z * xs1;

        float Aa = da0, Ba = db0;
        float Ab = da1, Bb = db1;
        #pragma unroll
        for (int ofs = 1; ofs < 32; ofs <<= 1){
            float aLa = __shfl_up_sync(0xffffffffu, Aa, ofs);
            float bLa = __shfl_up_sync(0xffffffffu, Ba, ofs);
            float aLb = __shfl_up_sync(0xffffffffu, Ab, ofs);
            float bLb = __shfl_up_sync(0xffffffffu, Bb, ofs);
            if (lane >= ofs){
                Ba = fmaf(bLa, Aa, Ba); Aa *= aLa;
                Bb = fmaf(bLb, Ab, Bb); Ab *= aLb;
            }
        }
        float h0 = fmaf(Aa, carry0, Ba);
        float h1 = fmaf(Ab, carry1, Bb);
        carry0 = __shfl_sync(0xffffffffu, h0, 31);
        carry1 = __shfl_sync(0xffffffffu, h1, 31);
        yrow0[l] = fmaf(p1.w, h0, Dv0 * xs0);
        yrow1[l] = fmaf(p1.w, h1, Dv1 * xs1);
    }
}

// ---------------- combine 4 directions + LayerNorm over channels ----------------
__global__ void __launch_bounds__(128) combln_kernel(
    const float* __restrict__ Ys, const float* __restrict__ T1T,
    const float* __restrict__ g, const float* __restrict__ bn,
    float* __restrict__ Yo)
{
    __shared__ float s[96*64];
    __shared__ float smu[64], srs[64];
    int b = blockIdx.y, lt = blockIdx.x, tid = threadIdx.x;
    int l0 = lt*64;
    for (int i = tid; i < 96*64; i += 128){
        int dd = i >> 6, j = i & 63;
        int l = l0 + j;
        size_t i0 = ((size_t)(b*4+0)*96 + dd)*Ln + l;
        size_t i2 = ((size_t)(b*4+2)*96 + dd)*Ln + (Ln-1-l);
        s[i] = Ys[i0] + Ys[i2] + T1T[((size_t)b*96 + dd)*Ln + l];
    }
    __syncthreads();
    if (tid < 64){
        float sum = 0.f, sq = 0.f;
        for (int dd = 0; dd < 96; dd++){
            float v = s[dd*64 + tid];
            sum += v; sq = fmaf(v, v, sq);
        }
        float mu  = sum * (1.f/96.f);
        float var = sq * (1.f/96.f) - mu*mu;
        smu[tid] = mu;
        srs[tid] = rsqrtf(var + 1e-5f);
    }
    __syncthreads();
    for (int i = tid; i < 96*64; i += 128){
        int dd = i >> 6, j = i & 63;
        Yo[((size_t)b*96 + dd)*Ln + l0 + j] = (s[i]-smu[j])*srs[j]*g[dd] + bn[dd];
    }
}

// ---------------- final LIF over T=4 and multiply by input x ----------------
__global__ void lif4_kernel(const float* __restrict__ Z, const float* __restrict__ X0,
                            float* __restrict__ Out){
    const int N = BB*PLANE;           // 1204224
    int i = blockIdx.x*blockDim.x + threadIdx.x;
    if (i >= N) return;
    float v = 0.f;
    #pragma unroll
    for (int t = 0; t < TT; t++){
        size_t idx = (size_t)t*N + i;
        float x = Z[idx];
        v += (x - v) * 0.5f;
        float sgn = (v >= 1.f) ? 1.f : 0.f;
        Out[idx] = sgn * X0[idx];
        v = (sgn > 0.f) ? 0.f : v;
    }
}

// ---------------- host launcher ----------------
extern "C" void kernel_launch(void* const* d_in, const int* in_sizes, int n_in,
                              void* d_out, int out_size)
{
    const float* x          = (const float*)d_in[0];
    const float* in_proj_w  = (const float*)d_in[1];
    const float* in_proj_b  = (const float*)d_in[2];
    const float* conv_w     = (const float*)d_in[3];
    const float* conv_b     = (const float*)d_in[4];
    const float* ssm_in_w   = (const float*)d_in[5];
    const float* ssm_conv_w = (const float*)d_in[6];
    const float* x_proj_w   = (const float*)d_in[7];
    const float* dt_proj_w  = (const float*)d_in[8];
    const float* dt_proj_b  = (const float*)d_in[9];
    const float* A_logs     = (const float*)d_in[10];
    const float* Ds         = (const float*)d_in[11];
    const float* ln_g       = (const float*)d_in[12];
    const float* ln_b       = (const float*)d_in[13];
    const float* out_proj_w = (const float*)d_in[14];
    float* out = (float*)d_out;

    float *bufA, *bufB, *bufT, *dbl, *ys, *wc, *wt;
    unsigned int* msk;
    cudaGetSymbolAddress((void**)&bufA, g_bufA);
    cudaGetSymbolAddress((void**)&bufB, g_bufB);
    cudaGetSymbolAddress((void**)&bufT, g_bufT);
    cudaGetSymbolAddress((void**)&dbl,  g_dbl);
    cudaGetSymbolAddress((void**)&ys,   g_ys);
    cudaGetSymbolAddress((void**)&wc,   g_wc);
    cudaGetSymbolAddress((void**)&wt,   g_wt);
    cudaGetSymbolAddress((void**)&msk,  g_msk);

    const int CONV_SMEM = 96*WPAD*4 + MROWS*MCOLS*3*4;   // 40416
    cudaFuncSetAttribute(conv3x3_kernel, cudaFuncAttributeMaxDynamicSharedMemorySize, CONV_SMEM);

    // 0. reorder conv weights + transpose gemm weights
    wreorder_kernel<<<(9*96*96 + 255)/256, 256>>>(conv_w, wc);
    wtrans_kernel<<<(3*9216 + 255)/256, 256>>>(in_proj_w, ssm_in_w, out_proj_w, wt);
    // 1. in_proj (+bias) -> bufA
    pw_gemm_kernel<<<dim3(49,16), 256>>>(x, wt, in_proj_b, bufA);
    // 2. LIF over 16 steps -> bitmasks
    lif16_kernel<<<(Ln*3 + 255)/256, 256>>>(bufA, msk);
    // 3. sparse full 3x3 conv + bias + silu -> bufA
    conv3x3_kernel<<<dim3(28,16), 256, CONV_SMEM>>>(msk, wc, conv_b, bufA);
    // 4. ssm_in pointwise -> bufB
    pw_gemm_kernel<<<dim3(49,16), 256>>>(bufA, wt + 9216, (const float*)nullptr, bufB);
    // 5+6. fused depthwise conv + silu -> bufA (= xe) and transposed -> bufT (= xeT)
    dwconvt_kernel<<<TBn*Cn, 256>>>(bufB, ssm_conv_w, bufA, bufT);
    // 7. x_proj for all 4 directions -> dbl
    projdbl_kernel<<<dim3(28,16), 112>>>(bufA, bufT, x_proj_w, dbl);
    // 8. fused selective scan (2 d-rows per warp) -> ys
    scan_kernel<<<64*12, 128>>>(bufA, bufT, dbl, dt_proj_w, dt_proj_b, A_logs, Ds, ys);
    // 9. (ys1 + rev(ys3)) + transpose fused -> bufT
    comb1t_kernel<<<TBn*Cn, 256>>>(ys, bufT);
    // 10. combine + LayerNorm -> bufA
    combln_kernel<<<dim3(49,16), 128>>>(ys, bufT, ln_g, ln_b, bufA);
    // 11. out_proj -> bufB
    pw_gemm_kernel<<<dim3(49,16), 256>>>(bufA, wt + 2*9216, (const float*)nullptr, bufB);
    // 12. final LIF(T=4) * x -> out
    lif4_kernel<<<(BB*PLANE + 255)/256, 256>>>(bufB, x, out);
}

// round 17
// speedup vs baseline: 1.1853x; 1.1784x over previous
#include <cuda_runtime.h>
#include <math.h>

#define TT 4
#define BB 4
#define TBn 16
#define Cn 96
#define Hn 56
#define Wn 56
#define Ln 3136
#define PLANE (Cn*Ln)          /* 301056 */
#define TOT (TBn*Cn*Ln)        /* 4816896 */

// ---------------- scratch (device globals; no allocation) ----------------
__device__ float g_bufA[TOT];
__device__ float g_bufB[TOT];
__device__ float g_bufT[TOT];
__device__ float g_dbl[TBn*4*Ln*8];     // (tb,k,l,8)
__device__ float g_ys[TBn*4*Cn*Ln];     // (tb,k,d,l) 77MB
__device__ float g_wc[9*Cn*Cn];         // conv weights reordered [tap][ci][co]
__device__ unsigned int g_msk[TBn*Ln*3];// spike bitmasks: [tb][l][3 words of 32 ch]

// ---------------- helpers ----------------
__device__ __forceinline__ float softplus_fast(float x){
    return (x > 15.f) ? x : __logf(1.f + __expf(x));
}
__device__ __forceinline__ float siluf(float v){
    return v * (1.f / (1.f + expf(-v)));
}

// packed fp32x2 helpers (Blackwell — elementwise IEEE fp32, 2 lanes/instr)
__device__ __forceinline__ unsigned long long pack2(float lo, float hi){
    unsigned long long r;
    asm("mov.b64 %0, {%1, %2};" : "=l"(r) : "r"(__float_as_uint(lo)), "r"(__float_as_uint(hi)));
    return r;
}
__device__ __forceinline__ void unpack2(unsigned long long v, float& lo, float& hi){
    unsigned int a, b;
    asm("mov.b64 {%0, %1}, %2;" : "=r"(a), "=r"(b) : "l"(v));
    lo = __uint_as_float(a); hi = __uint_as_float(b);
}
#define FMA2(acc, a, b) asm("fma.rn.f32x2 %0, %1, %2, %0;" : "+l"(acc) : "l"(a), "l"(b))

// ---------------- conv weight reorder: (co,ci,ky,kx) -> [tap][ci][co] ----------------
__global__ void wreorder_kernel(const float* __restrict__ Win, float* __restrict__ Wt){
    int i = blockIdx.x*blockDim.x + threadIdx.x;
    if (i >= 9*96*96) return;
    int tap = i % 9;
    int ci  = (i / 9) % 96;
    int co  = i / (9*96);
    Wt[tap*9216 + ci*96 + co] = Win[i];
}

// ---------------- pointwise 96x96 GEMM (R13 proven: smem weights stride 98, FFMA2) ---------
#define GSTR 98
__global__ void __launch_bounds__(256) pw_gemm_kernel(
    const float* __restrict__ X, const float* __restrict__ Wm,
    const float* __restrict__ bias, float* __restrict__ Y)
{
    extern __shared__ float sm[];
    float* Ws = sm;                 // [k][co] stride 98
    float* Xs = sm + 96*GSTR;       // [k][64]
    int tb = blockIdx.y;
    int lt = blockIdx.x;
    int tid = threadIdx.x;

    for (int i = tid; i < 96*96; i += 256){
        int co = i / 96, k = i - co*96;
        Ws[k*GSTR + co] = Wm[i];
    }
    const float* Xp = X + (size_t)tb*PLANE + lt*64;
    for (int i = tid; i < 96*64; i += 256){
        int k = i >> 6, j = i & 63;
        Xs[i] = Xp[(size_t)k*Ln + j];
    }
    __syncthreads();

    int tx = tid & 15, ty = tid >> 4;
    unsigned long long acc[6][2];
    #pragma unroll
    for (int i = 0; i < 6; i++){ acc[i][0] = 0ull; acc[i][1] = 0ull; }

    #pragma unroll 4
    for (int k = 0; k < 96; k++){
        float4 a = *(const float4*)(Xs + k*64 + tx*4);
        unsigned long long x01 = pack2(a.x, a.y);
        unsigned long long x23 = pack2(a.z, a.w);
        const float2* wrow = (const float2*)(Ws + k*GSTR + ty*6);
        float2 w01 = wrow[0], w23 = wrow[1], w45 = wrow[2];
        float wv[6] = {w01.x, w01.y, w23.x, w23.y, w45.x, w45.y};
        #pragma unroll
        for (int i = 0; i < 6; i++){
            unsigned long long ww = pack2(wv[i], wv[i]);
            FMA2(acc[i][0], ww, x01);
            FMA2(acc[i][1], ww, x23);
        }
    }
    #pragma unroll
    for (int i = 0; i < 6; i++){
        int co = ty*6 + i;
        float bv = bias ? bias[co] : 0.f;
        float o0, o1, o2, o3;
        unpack2(acc[i][0], o0, o1);
        unpack2(acc[i][1], o2, o3);
        float* yp = Y + (size_t)tb*PLANE + (size_t)co*Ln + lt*64 + tx*4;
        *(float4*)yp = make_float4(o0+bv, o1+bv, o2+bv, o3+bv);
    }
}

// ---------------- LIF over 16 steps -> channel bitmasks (8 ch/thread, byte writes) ---------
__global__ void lif16_kernel(const float* __restrict__ X, unsigned char* __restrict__ M8){
    int tid = blockIdx.x*blockDim.x + threadIdx.x;
    if (tid >= Ln*12) return;
    int w8 = tid / Ln;                 // 0..11 (byte index, 8 channels each)
    int l  = tid - w8*Ln;
    float v[8];
    #pragma unroll
    for (int c = 0; c < 8; c++) v[c] = 0.f;
    for (int t = 0; t < TBn; t++){
        unsigned int m = 0u;
        #pragma unroll
        for (int c = 0; c < 8; c++){
            float x = X[((size_t)t*Cn + w8*8 + c)*Ln + l];
            v[c] += (x - v[c]) * 0.5f;
            bool s = (v[c] >= 1.0f);
            if (s) m |= (1u << c);
            v[c] = s ? 0.f : v[c];
        }
        M8[((size_t)t*Ln + l)*12 + w8] = (unsigned char)m;
    }
}

// ---------------- sparse full 3x3 conv (R10 proven config) ----------------
#define MROWS 4
#define MCOLS 58
#define WPAD 98
__global__ void __launch_bounds__(256, 3) conv3x3_kernel(
    const unsigned int* __restrict__ Msk, const float* __restrict__ Wt,
    const float* __restrict__ bias, float* __restrict__ Y)
{
    extern __shared__ float sm[];
    float* Ws = sm;                               // 96*98 floats (current tap, padded)
    unsigned int* Mh = (unsigned int*)(sm + 96*WPAD);  // 4*58*3 u32
    int tb = blockIdx.y, rt = blockIdx.x, tid = threadIdx.x;
    int h0 = rt*2;
    const unsigned int* Mp = Msk + (size_t)tb*Ln*3;

    for (int i = tid; i < MROWS*MCOLS*3; i += 256){
        int r = i / (MCOLS*3);
        int rem = i - r*(MCOLS*3);
        int c = rem / 3, w = rem - c*3;
        int h = h0 - 1 + r;
        int ww = c - 1;
        unsigned int v = 0u;
        if (h >= 0 && h < 56 && ww >= 0 && ww < 56)
            v = Mp[((size_t)h*56 + ww)*3 + w];
        Mh[i] = v;
    }

    int tx = tid & 15, ty = tid >> 4;
    int co0 = ty*6;
    int pbase[7];
    #pragma unroll
    for (int j = 0; j < 7; j++){
        int lp = tx*7 + j;                 // 0..111
        int ro = lp / 56, w = lp - ro*56;
        pbase[j] = ((ro+1)*MCOLS + (w+1))*3;
    }
    float acc[6][7];
    #pragma unroll
    for (int i = 0; i < 6; i++)
        #pragma unroll
        for (int j = 0; j < 7; j++) acc[i][j] = 0.f;

    for (int tap = 0; tap < 9; tap++){
        __syncthreads();
        const float* wp = Wt + tap*9216;
        for (int i = tid; i < 9216; i += 256){
            int k = i / 96, co = i - k*96;
            Ws[k*WPAD + co] = wp[i];
        }
        __syncthreads();
        int dy = tap/3 - 1;
        int dx = tap - (tap/3)*3 - 1;
        int toff = (dy*MCOLS + dx)*3;

        #pragma unroll
        for (int j = 0; j < 7; j++){
            const unsigned int* mp = Mh + pbase[j] + toff;
            #pragma unroll
            for (int w3 = 0; w3 < 3; w3++){
                unsigned int m = mp[w3];
                while (m){
                    int b = __ffs(m) - 1;
                    m &= (m - 1u);
                    int k = w3*32 + b;
                    const float2* rp = (const float2*)(Ws + k*WPAD + co0);
                    float2 w01 = rp[0], w23 = rp[1], w45 = rp[2];
                    acc[0][j] += w01.x;
                    acc[1][j] += w01.y;
                    acc[2][j] += w23.x;
                    acc[3][j] += w23.y;
                    acc[4][j] += w45.x;
                    acc[5][j] += w45.y;
                }
            }
        }
    }
    int l0 = h0*56;
    #pragma unroll
    for (int i = 0; i < 6; i++){
        int co = co0 + i;
        float bv = bias[co];
        float* yp = Y + (size_t)tb*PLANE + (size_t)co*Ln + l0 + tx*7;
        #pragma unroll
        for (int j = 0; j < 7; j++)
            yp[j] = siluf(acc[i][j] + bv);
    }
}

// ---------------- fused depthwise 3x3 conv + silu + dual (normal/transposed) write ---------
__global__ void __launch_bounds__(256) dwconvt_kernel(
    const float* __restrict__ X, const float* __restrict__ Wd,
    float* __restrict__ Xe, float* __restrict__ XeT)
{
    __shared__ float s[Ln];
    __shared__ float o[Ln];
    int p = blockIdx.x;                 // tb*96 + d
    int d = p % 96;
    const float* xp = X + (size_t)p*Ln;
    int tid = threadIdx.x;
    for (int i = tid; i < Ln; i += 256) s[i] = xp[i];
    float w[9];
    #pragma unroll
    for (int j = 0; j < 9; j++) w[j] = Wd[d*9 + j];
    __syncthreads();
    for (int i = tid; i < Ln; i += 256){
        int h = i / 56, ww = i - h*56;
        float a = 0.f;
        #pragma unroll
        for (int dy = -1; dy <= 1; dy++){
            int hh = h + dy;
            if (hh < 0 || hh >= 56) continue;
            #pragma unroll
            for (int dx = -1; dx <= 1; dx++){
                int cc = ww + dx;
                if (cc < 0 || cc >= 56) continue;
                a = fmaf(w[(dy+1)*3 + (dx+1)], s[hh*56 + cc], a);
            }
        }
        o[i] = siluf(a);
    }
    __syncthreads();
    float* ye = Xe + (size_t)p*Ln;
    float* yt = XeT + (size_t)p*Ln;
    for (int i = tid; i < Ln; i += 256){
        ye[i] = o[i];
        int a = i / 56, b = i - a*56;
        yt[i] = o[b*56 + a];
    }
}

// ---------------- fused (ys1 + rev(ys3)) then transpose ----------------
__global__ void comb1t_kernel(const float* __restrict__ Ys, float* __restrict__ T1T){
    __shared__ float s[Ln];
    int p = blockIdx.x;                 // (tb*96 + d)
    int tb = p / 96, d = p - tb*96;
    const float* y1 = Ys + ((size_t)(tb*4+1)*96 + d)*Ln;
    const float* y3 = Ys + ((size_t)(tb*4+3)*96 + d)*Ln;
    float* yp = T1T + (size_t)p*Ln;
    for (int i = threadIdx.x; i < Ln; i += blockDim.x)
        s[i] = y1[i] + y3[Ln-1-i];
    __syncthreads();
    for (int i = threadIdx.x; i < Ln; i += blockDim.x){
        int a = i / 56, b = i - a*56;
        yp[i] = s[b*56 + a];
    }
}

// ---------------- dbl projection v2: 112 threads, one l/thread, [d][k][r] weights ----------
__global__ void __launch_bounds__(112) projdbl_kernel(
    const float* __restrict__ Xe, const float* __restrict__ XeT,
    const float* __restrict__ Wp, float* __restrict__ Dbl)
{
    __shared__ float sw[3072];          // [d][k][r]: sw[d*32 + k*8 + r]
    int tb = blockIdx.y, lt = blockIdx.x, tid = threadIdx.x;
    for (int i = tid; i < 3072; i += 112){
        int d = i >> 5, rem = i & 31;
        int k = rem >> 3, r = rem & 7;
        sw[i] = Wp[k*768 + r*96 + d];
    }
    __syncthreads();

    int l = lt*112 + tid;
    const float* xe = Xe + (size_t)tb*PLANE + l;
    const float* xt = XeT + (size_t)tb*PLANE + l;

    float a0[8], a1[8], a2[8], a3[8];
    #pragma unroll
    for (int r = 0; r < 8; r++){ a0[r]=0.f; a1[r]=0.f; a2[r]=0.f; a3[r]=0.f; }

    #pragma unroll 2
    for (int d = 0; d < 96; d++){
        float ev = xe[(size_t)d*Ln];
        float tv = xt[(size_t)d*Ln];
        const float2* wd = (const float2*)(sw + d*32);
        #pragma unroll
        for (int r2 = 0; r2 < 4; r2++){
            float2 p0 = wd[r2];
            float2 p1 = wd[4 + r2];
            float2 p2 = wd[8 + r2];
            float2 p3 = wd[12 + r2];
            a0[r2*2]   = fmaf(ev, p0.x, a0[r2*2]);
            a0[r2*2+1] = fmaf(ev, p0.y, a0[r2*2+1]);
            a1[r2*2]   = fmaf(tv, p1.x, a1[r2*2]);
            a1[r2*2+1] = fmaf(tv, p1.y, a1[r2*2+1]);
            a2[r2*2]   = fmaf(ev, p2.x, a2[r2*2]);
            a2[r2*2+1] = fmaf(ev, p2.y, a2[r2*2+1]);
            a3[r2*2]   = fmaf(tv, p3.x, a3[r2*2]);
            a3[r2*2+1] = fmaf(tv, p3.y, a3[r2*2+1]);
        }
    }
    int lr = Ln - 1 - l;
    size_t o0 = ((size_t)(tb*4+0)*Ln + l )*8;
    size_t o1 = ((size_t)(tb*4+1)*Ln + l )*8;
    size_t o2 = ((size_t)(tb*4+2)*Ln + lr)*8;
    size_t o3 = ((size_t)(tb*4+3)*Ln + lr)*8;
    *(float4*)(Dbl+o0)   = make_float4(a0[0],a0[1],a0[2],a0[3]);
    *(float4*)(Dbl+o0+4) = make_float4(a0[4],a0[5],a0[6],a0[7]);
    *(float4*)(Dbl+o1)   = make_float4(a1[0],a1[1],a1[2],a1[3]);
    *(float4*)(Dbl+o1+4) = make_float4(a1[4],a1[5],a1[6],a1[7]);
    *(float4*)(Dbl+o2)   = make_float4(a2[0],a2[1],a2[2],a2[3]);
    *(float4*)(Dbl+o2+4) = make_float4(a2[4],a2[5],a2[6],a2[7]);
    *(float4*)(Dbl+o3)   = make_float4(a3[0],a3[1],a3[2],a3[3]);
    *(float4*)(Dbl+o3+4) = make_float4(a3[4],a3[5],a3[6],a3[7]);
}

// ---------------- fused selective scan: warp scans 2 d-rows, sharing dbl loads -------------
__global__ void __launch_bounds__(128) scan_kernel(
    const float* __restrict__ Xe, const float* __restrict__ XeT,
    const float* __restrict__ Dbl,
    const float* __restrict__ DtW, const float* __restrict__ DtB,
    const float* __restrict__ Alog, const float* __restrict__ DsP,
    float* __restrict__ Ys)
{
    int warp = threadIdx.x >> 5, lane = threadIdx.x & 31;
    int bid = blockIdx.x;                 // 64*12 blocks
    int bk = bid / 12;                    // tb*4+k
    int dg = bid - bk*12;                 // 0..11
    int d0 = dg*8 + warp*2;               // this warp: d0, d0+1
    int b  = bk >> 2, k = bk & 3;
    int kd0 = k*96 + d0;
    int kd1 = kd0 + 1;

    float u0 = DtW[kd0*6+0], u1 = DtW[kd0*6+1], u2 = DtW[kd0*6+2];
    float u3 = DtW[kd0*6+3], u4 = DtW[kd0*6+4], u5 = DtW[kd0*6+5];
    float v0 = DtW[kd1*6+0], v1 = DtW[kd1*6+1], v2 = DtW[kd1*6+2];
    float v3 = DtW[kd1*6+3], v4 = DtW[kd1*6+4], v5 = DtW[kd1*6+5];
    float bdt0 = DtB[kd0], bdt1 = DtB[kd1];
    float A0 = -expf(Alog[kd0]), A1 = -expf(Alog[kd1]);
    float Dv0 = DsP[kd0], Dv1 = DsP[kd1];

    const float* xbase = ((k & 1) ? XeT : Xe) + (size_t)(b*96 + d0)*Ln;
    const float* xrow0 = xbase;
    const float* xrow1 = xbase + Ln;
    const float* dp = Dbl + (size_t)bk*Ln*8;
    float* yrow0 = Ys + ((size_t)bk*96 + d0)*Ln;
    float* yrow1 = yrow0 + Ln;
    bool rev = (k >= 2);

    float carry0 = 0.f, carry1 = 0.f;
    for (int j = 0; j < 98; j++){
        int l = j*32 + lane;
        float4 p0 = *(const float4*)(dp + (size_t)l*8);
        float4 p1 = *(const float4*)(dp + (size_t)l*8 + 4);
        int lx = rev ? (Ln-1-l) : l;
        float xs0 = xrow0[lx];
        float xs1 = xrow1[lx];

        float dtr0 = bdt0 + p0.x*u0 + p0.y*u1 + p0.z*u2 + p0.w*u3 + p1.x*u4 + p1.y*u5;
        float dtr1 = bdt1 + p0.x*v0 + p0.y*v1 + p0.z*v2 + p0.w*v3 + p1.x*v4 + p1.y*v5;
        float sp0 = softplus_fast(dtr0);
        float sp1 = softplus_fast(dtr1);
        float da0 = __expf(sp0 * A0);
        float da1 = __expf(sp1 * A1);
        float db0 = sp0 * p1.z * xs0;
        float db1 = sp1 * p1.z * xs1;

        float Aa = da0, Ba = db0;
        float Ab = da1, Bb = db1;
        #pragma unroll
        for (int ofs = 1; ofs < 32; ofs <<= 1){
            float aLa = __shfl_up_sync(0xffffffffu, Aa, ofs);
            float bLa = __shfl_up_sync(0xffffffffu, Ba, ofs);
            float aLb = __shfl_up_sync(0xffffffffu, Ab, ofs);
            float bLb = __shfl_up_sync(0xffffffffu, Bb, ofs);
            if (lane >= ofs){
                Ba = fmaf(bLa, Aa, Ba); Aa *= aLa;
                Bb = fmaf(bLb, Ab, Bb); Ab *= aLb;
            }
        }
        float h0 = fmaf(Aa, carry0, Ba);
        float h1 = fmaf(Ab, carry1, Bb);
        carry0 = __shfl_sync(0xffffffffu, h0, 31);
        carry1 = __shfl_sync(0xffffffffu, h1, 31);
        yrow0[l] = fmaf(p1.w, h0, Dv0 * xs0);
        yrow1[l] = fmaf(p1.w, h1, Dv1 * xs1);
    }
}

// ---------------- combine 4 directions + LayerNorm over channels ----------------
__global__ void __launch_bounds__(128) combln_kernel(
    const float* __restrict__ Ys, const float* __restrict__ T1T,
    const float* __restrict__ g, const float* __restrict__ bn,
    float* __restrict__ Yo)
{
    __shared__ float s[96*64];
    __shared__ float smu[64], srs[64];
    int b = blockIdx.y, lt = blockIdx.x, tid = threadIdx.x;
    int l0 = lt*64;
    for (int i = tid; i < 96*64; i += 128){
        int dd = i >> 6, j = i & 63;
        int l = l0 + j;
        size_t i0 = ((size_t)(b*4+0)*96 + dd)*Ln + l;
        size_t i2 = ((size_t)(b*4+2)*96 + dd)*Ln + (Ln-1-l);
        s[i] = Ys[i0] + Ys[i2] + T1T[((size_t)b*96 + dd)*Ln + l];
    }
    __syncthreads();
    if (tid < 64){
        float sum = 0.f, sq = 0.f;
        for (int dd = 0; dd < 96; dd++){
            float v = s[dd*64 + tid];
            sum += v; sq = fmaf(v, v, sq);
        }
        float mu  = sum * (1.f/96.f);
        float var = sq * (1.f/96.f) - mu*mu;
        smu[tid] = mu;
        srs[tid] = rsqrtf(var + 1e-5f);
    }
    __syncthreads();
    for (int i = tid; i < 96*64; i += 128){
        int dd = i >> 6, j = i & 63;
        Yo[((size_t)b*96 + dd)*Ln + l0 + j] = (s[i]-smu[j])*srs[j]*g[dd] + bn[dd];
    }
}

// ---------------- final LIF over T=4 and multiply by input x ----------------
__global__ void lif4_kernel(const float* __restrict__ Z, const float* __restrict__ X0,
                            float* __restrict__ Out){
    const int N = BB*PLANE;           // 1204224
    int i = blockIdx.x*blockDim.x + threadIdx.x;
    if (i >= N) return;
    float v = 0.f;
    #pragma unroll
    for (int t = 0; t < TT; t++){
        size_t idx = (size_t)t*N + i;
        float x = Z[idx];
        v += (x - v) * 0.5f;
        float sgn = (v >= 1.f) ? 1.f : 0.f;
        Out[idx] = sgn * X0[idx];
        v = (sgn > 0.f) ? 0.f : v;
    }
}

// ---------------- host launcher ----------------
extern "C" void kernel_launch(void* const* d_in, const int* in_sizes, int n_in,
                              void* d_out, int out_size)
{
    const float* x          = (const float*)d_in[0];
    const float* in_proj_w  = (const float*)d_in[1];
    const float* in_proj_b  = (const float*)d_in[2];
    const float* conv_w     = (const float*)d_in[3];
    const float* conv_b     = (const float*)d_in[4];
    const float* ssm_in_w   = (const float*)d_in[5];
    const float* ssm_conv_w = (const float*)d_in[6];
    const float* x_proj_w   = (const float*)d_in[7];
    const float* dt_proj_w  = (const float*)d_in[8];
    const float* dt_proj_b  = (const float*)d_in[9];
    const float* A_logs     = (const float*)d_in[10];
    const float* Ds         = (const float*)d_in[11];
    const float* ln_g       = (const float*)d_in[12];
    const float* ln_b       = (const float*)d_in[13];
    const float* out_proj_w = (const float*)d_in[14];
    float* out = (float*)d_out;

    float *bufA, *bufB, *bufT, *dbl, *ys, *wc;
    unsigned int* msk;
    cudaGetSymbolAddress((void**)&bufA, g_bufA);
    cudaGetSymbolAddress((void**)&bufB, g_bufB);
    cudaGetSymbolAddress((void**)&bufT, g_bufT);
    cudaGetSymbolAddress((void**)&dbl,  g_dbl);
    cudaGetSymbolAddress((void**)&ys,   g_ys);
    cudaGetSymbolAddress((void**)&wc,   g_wc);
    cudaGetSymbolAddress((void**)&msk,  g_msk);

    const int GEMM_SMEM = (96*GSTR + 96*64)*4;           // 62208
    const int CONV_SMEM = 96*WPAD*4 + MROWS*MCOLS*3*4;   // 40416
    cudaFuncSetAttribute(pw_gemm_kernel, cudaFuncAttributeMaxDynamicSharedMemorySize, GEMM_SMEM);
    cudaFuncSetAttribute(conv3x3_kernel, cudaFuncAttributeMaxDynamicSharedMemorySize, CONV_SMEM);

    // 0. reorder conv weights
    wreorder_kernel<<<(9*96*96 + 255)/256, 256>>>(conv_w, wc);
    // 1. in_proj (+bias) -> bufA
    pw_gemm_kernel<<<dim3(49,16), 256, GEMM_SMEM>>>(x, in_proj_w, in_proj_b, bufA);
    // 2. LIF over 16 steps -> bitmasks (8 ch/thread, 4x parallelism)
    lif16_kernel<<<(Ln*12 + 255)/256, 256>>>(bufA, (unsigned char*)msk);
    // 3. sparse full 3x3 conv + bias + silu -> bufA
    conv3x3_kernel<<<dim3(28,16), 256, CONV_SMEM>>>(msk, wc, conv_b, bufA);
    // 4. ssm_in pointwise -> bufB
    pw_gemm_kernel<<<dim3(49,16), 256, GEMM_SMEM>>>(bufA, ssm_in_w, (const float*)nullptr, bufB);
    // 5+6. fused depthwise conv + silu -> bufA (= xe) and transposed -> bufT (= xeT)
    dwconvt_kernel<<<TBn*Cn, 256>>>(bufB, ssm_conv_w, bufA, bufT);
    // 7. x_proj for all 4 directions -> dbl
    projdbl_kernel<<<dim3(28,16), 112>>>(bufA, bufT, x_proj_w, dbl);
    // 8. fused selective scan (2 d-rows per warp) -> ys
    scan_kernel<<<64*12, 128>>>(bufA, bufT, dbl, dt_proj_w, dt_proj_b, A_logs, Ds, ys);
    // 9. (ys1 + rev(ys3)) + transpose fused -> bufT
    comb1t_kernel<<<TBn*Cn, 256>>>(ys, bufT);
    // 10. combine + LayerNorm -> bufA
    combln_kernel<<<dim3(49,16), 128>>>(ys, bufT, ln_g, ln_b, bufA);
    // 11. out_proj -> bufB
    pw_gemm_kernel<<<dim3(49,16), 256, GEMM_SMEM>>>(bufA, out_proj_w, (const float*)nullptr, bufB);
    // 12. final LIF(T=4) * x -> out
    lif4_kernel<<<(BB*PLANE + 255)/256, 256>>>(bufB, x, out);
}